// round 4
// baseline (speedup 1.0000x reference)
#include <cuda_runtime.h>
#include <cuda_bf16.h>

// SAN Subtraction: out[n,c,kk,p] = x[n,c,h,w] - reflectpad(x)[n,c,h+kh,w+kw]
// N=4, C=64, H=W=112, K=7, PAD=3, reflect. out (N,C,49,12544) fp32 = 630 MB writes.
// v4: - vectorized neighbor loads: 3 aligned LDG.128 cover the 10-float span;
//       reflect edge fixups are pure register moves (reflected values already loaded)
//     - kh-outer / step-middle / kw-inner: block writes only 7 streams per kh,
//       7KB contiguous per stream (DRAM page locality), vs 49 interleaved streams
//     - center row float4s cached in registers across the whole kh loop
//     - streaming stores (__stcs), occupancy ~65%

#define H 112
#define W 112
#define KS 7
#define PADV 3
#define HW (H * W)            // 12544
#define CC 64
#define NN 4
#define W4N 28                // float4s per row
#define TPB 224               // 7 warps; one step stride = 224 fl4 = exactly 8 rows
#define STEPS 2               // block tile = 448 fl4 = 16 rows; 7 blocks/plane

__device__ __forceinline__ int reflect_h(int j) {
    j = j < 0 ? -j : j;
    j = j >= H ? (2 * (H - 1) - j) : j;
    return j;
}

__global__ void __launch_bounds__(TPB, 6) san_sub_kernel(
    const float* __restrict__ x, float* __restrict__ out)
{
    const int i0 = blockIdx.x * (TPB * STEPS) + threadIdx.x; // fl4 idx, step 0
    const int h0 = i0 / W4N;
    const int w4 = (i0 - h0 * W4N) << 2;                     // constant across steps
    const int plane = blockIdx.z * CC + blockIdx.y;

    const bool pL = (w4 != 0);
    const bool pR = (w4 != W - 4);

    const float* xp = x + (size_t)plane * HW;
    float* op = out + (size_t)plane * (KS * KS) * HW;

    // center float4 per step (step s -> row h0 + 8*s, same w4)
    float4 ctr[STEPS];
    #pragma unroll
    for (int s = 0; s < STEPS; ++s)
        ctr[s] = *reinterpret_cast<const float4*>(xp + (i0 + s * TPB) * 4);

    #pragma unroll
    for (int kh = 0; kh < KS; ++kh) {
        #pragma unroll
        for (int s = 0; s < STEPS; ++s) {
            const int h  = h0 + (s << 3);
            const int rh = reflect_h(h + kh - PADV);
            const float* row = xp + rh * W;

            // v[j] = x[row, w4-4+j] for j=0..11 (interior); edges fixed below
            float v[12];
            if (pL) *reinterpret_cast<float4*>(&v[0]) =
                        *reinterpret_cast<const float4*>(row + w4 - 4);
            *reinterpret_cast<float4*>(&v[4]) =
                        *reinterpret_cast<const float4*>(row + w4);
            if (pR) *reinterpret_cast<float4*>(&v[8]) =
                        *reinterpret_cast<const float4*>(row + w4 + 4);
            if (!pL) {                 // w4==0: reflect(-1,-2,-3) = x[1],x[2],x[3]
                v[3] = v[5]; v[2] = v[6]; v[1] = v[7];
            }
            if (!pR) {                 // w4==108: reflect(112,113,114) = x[110,109,108]
                v[8] = v[6]; v[9] = v[5]; v[10] = v[4];
            }

            const float4 c = ctr[s];
            float* ob = op + (size_t)(kh * KS) * HW + (size_t)(i0 + s * TPB) * 4;
            #pragma unroll
            for (int kw = 0; kw < KS; ++kw) {
                float4 o;
                o.x = c.x - v[kw + 1];
                o.y = c.y - v[kw + 2];
                o.z = c.z - v[kw + 3];
                o.w = c.w - v[kw + 4];
                __stcs(reinterpret_cast<float4*>(ob + (size_t)kw * HW), o);
            }
        }
    }
}

extern "C" void kernel_launch(void* const* d_in, const int* in_sizes, int n_in,
                              void* d_out, int out_size) {
    const float* x = (const float*)d_in[0];
    float* out = (float*)d_out;
    dim3 block(TPB, 1, 1);
    dim3 grid(HW / 4 / (TPB * STEPS), CC, NN);   // (7, 64, 4) = 1792 blocks
    san_sub_kernel<<<grid, block>>>(x, out);
}